// round 3
// baseline (speedup 1.0000x reference)
#include <cuda_runtime.h>
#include <cstdint>

// ---------------------------------------------------------------------------
// GCN1: x3 = adj@( adj@( dropout(relu(adj@(x@W1)+b1)) @ W2 + b2 ) @ W3 ) + b3
// Shapes: x 10000x1024, adj 10000x10000, W1 1024x512, W2 512x256, W3 256x128.
// All fp32 row-major. Dropout mask = JAX *partitionable* threefry2x32,
// key (0,42), p=0.5: per-element 64-bit counter i -> pair (hi=0, lo=i),
// 32-bit draw = out0 ^ out1 (the bit_width==32 branch), keep <=> top bit == 0.
// ---------------------------------------------------------------------------

static __device__ float g_buf1[10000 * 512];
static __device__ float g_buf2[10000 * 512];

__device__ __forceinline__ unsigned rotl32(unsigned v, int s) {
    return (v << s) | (v >> (32 - s));
}

// JAX partitionable threefry2x32, key (0, 42).
// counts = iota(uint64, size); pair = (hi32(i), lo32(i)) = (0, i) for i < 2^32.
// 32-bit draw = out0 ^ out1 ; uniform<0.5  <=>  top bit of draw == 0.
__device__ __forceinline__ bool dropout_keep(unsigned idx) {
    const unsigned ks0 = 0u, ks1 = 42u;
    const unsigned ks2 = 0x1BD11BDAu ^ ks0 ^ ks1;
    unsigned x0 = 0u + ks0;       // counter hi word = 0
    unsigned x1 = idx + ks1;      // counter lo word = idx
#define TF_R(r) { x0 += x1; x1 = rotl32(x1, (r)); x1 ^= x0; }
    TF_R(13) TF_R(15) TF_R(26) TF_R(6)
    x0 += ks1; x1 += ks2 + 1u;
    TF_R(17) TF_R(29) TF_R(16) TF_R(24)
    x0 += ks2; x1 += ks0 + 2u;
    TF_R(13) TF_R(15) TF_R(26) TF_R(6)
    x0 += ks0; x1 += ks1 + 3u;
    TF_R(17) TF_R(29) TF_R(16) TF_R(24)
    x0 += ks1; x1 += ks2 + 4u;
    TF_R(13) TF_R(15) TF_R(26) TF_R(6)
    x0 += ks2; x1 += ks0 + 5u;
#undef TF_R
    return ((x0 ^ x1) & 0x80000000u) == 0u;
}

// ---------------------------------------------------------------------------
// Tiled fp32 GEMM: C[M,N] = A[M,K] @ B[K,N] (+bias) (+relu+dropout)
// BM=128, BN=64, BK=8; 256 threads; 8x4 accumulators per thread.
// Requires: N % 64 == 0, K % 8 == 0 (true for all 6 calls). M guarded.
// EPI: 0 = none, 1 = +bias, 2 = +bias, relu, dropout(threefry)
// ---------------------------------------------------------------------------
constexpr int BM = 128, BN = 64, BK = 8, TM = 8, TN = 4;

template <int EPI>
__global__ __launch_bounds__(256)
void gemm_kernel(const float* __restrict__ A, const float* __restrict__ B,
                 const float* __restrict__ bias, float* __restrict__ C,
                 int M, int N, int K)
{
    __shared__ __align__(16) float As[BK][BM];   // transposed A tile
    __shared__ __align__(16) float Bs[BK][BN];

    const int tid = threadIdx.x;
    const int tx = tid & 15;    // 0..15 -> column group (TN=4 wide)
    const int ty = tid >> 4;    // 0..15 -> row group    (TM=8 tall)
    const int bm0 = blockIdx.y * BM;
    const int bn0 = blockIdx.x * BN;

    // A tile loads: 128x8 = 1024 floats / 256 thr = one float4 each (along K)
    const int aRow = tid >> 1;          // 0..127
    const int aK   = (tid & 1) * 4;     // 0 or 4
    // B tile loads: 8x64 = 512 floats / 256 thr = one float2 each
    const int bRow = tid >> 5;          // 0..7
    const int bCol = (tid & 31) * 2;    // 0..62

    const int gARow = bm0 + aRow;
    const bool aValid = gARow < M;
    const float* Aptr = A + (size_t)gARow * K + aK;
    const float* Bptr = B + (size_t)bRow * N + bn0 + bCol;

    float acc[TM][TN];
#pragma unroll
    for (int i = 0; i < TM; i++)
#pragma unroll
        for (int j = 0; j < TN; j++) acc[i][j] = 0.0f;

    const int numTiles = K / BK;

    float4 aReg = aValid ? *(const float4*)Aptr : make_float4(0.f, 0.f, 0.f, 0.f);
    float2 bReg = *(const float2*)Bptr;

    for (int t = 0; t < numTiles; ++t) {
        As[aK + 0][aRow] = aReg.x;
        As[aK + 1][aRow] = aReg.y;
        As[aK + 2][aRow] = aReg.z;
        As[aK + 3][aRow] = aReg.w;
        Bs[bRow][bCol]     = bReg.x;
        Bs[bRow][bCol + 1] = bReg.y;
        __syncthreads();

        // prefetch next tile into registers while computing this one
        if (t + 1 < numTiles) {
            const float* An = Aptr + (size_t)(t + 1) * BK;
            const float* Bn = Bptr + (size_t)(t + 1) * BK * N;
            aReg = aValid ? *(const float4*)An : make_float4(0.f, 0.f, 0.f, 0.f);
            bReg = *(const float2*)Bn;
        }

#pragma unroll
        for (int kk = 0; kk < BK; ++kk) {
            const float4 a0 = *(const float4*)&As[kk][ty * TM];
            const float4 a1 = *(const float4*)&As[kk][ty * TM + 4];
            const float4 bv = *(const float4*)&Bs[kk][tx * TN];
            const float a[TM] = {a0.x, a0.y, a0.z, a0.w, a1.x, a1.y, a1.z, a1.w};
            const float b[TN] = {bv.x, bv.y, bv.z, bv.w};
#pragma unroll
            for (int i = 0; i < TM; i++)
#pragma unroll
                for (int j = 0; j < TN; j++)
                    acc[i][j] = fmaf(a[i], b[j], acc[i][j]);
        }
        __syncthreads();
    }

    // Epilogue (vectorized float4 column stores; columns contiguous per thread)
    const int c0 = bn0 + tx * TN;
    float4 bias4 = make_float4(0.f, 0.f, 0.f, 0.f);
    if (EPI >= 1) bias4 = *(const float4*)&bias[c0];

#pragma unroll
    for (int i = 0; i < TM; i++) {
        const int r = bm0 + ty * TM + i;
        if (r < M) {
            float v[TN];
#pragma unroll
            for (int j = 0; j < TN; j++) {
                float val = acc[i][j];
                if (EPI >= 1) val += (&bias4.x)[j];
                if (EPI == 2) {
                    val = fmaxf(val, 0.0f);
                    const unsigned idx = (unsigned)r * (unsigned)N + (unsigned)(c0 + j);
                    val = dropout_keep(idx) ? val * 2.0f : 0.0f;
                }
                v[j] = val;
            }
            *(float4*)&C[(size_t)r * N + c0] = make_float4(v[0], v[1], v[2], v[3]);
        }
    }
}

extern "C" void kernel_launch(void* const* d_in, const int* in_sizes, int n_in,
                              void* d_out, int out_size)
{
    const float* x   = (const float*)d_in[0];
    const float* adj = (const float*)d_in[1];
    const float* W1  = (const float*)d_in[2];
    const float* b1  = (const float*)d_in[3];
    const float* W2  = (const float*)d_in[4];
    const float* b2  = (const float*)d_in[5];
    const float* W3  = (const float*)d_in[6];
    const float* b3  = (const float*)d_in[7];
    float* out = (float*)d_out;

    float *buf1, *buf2;
    cudaGetSymbolAddress((void**)&buf1, g_buf1);
    cudaGetSymbolAddress((void**)&buf2, g_buf2);

    const int M = 10000;
    dim3 blk(256);
    auto grid = [&](int N) { return dim3((N + BN - 1) / BN, (M + BM - 1) / BM); };

    // Layer 1: H = x @ W1 ; X1 = dropout(relu(adj @ H + b1))
    gemm_kernel<0><<<grid(512), blk>>>(x,   W1, nullptr, buf1, M, 512, 1024);
    gemm_kernel<2><<<grid(512), blk>>>(adj, buf1, b1,    buf2, M, 512, M);
    // Layer 2: T = X1 @ W2 ; X2 = adj @ T + b2
    gemm_kernel<0><<<grid(256), blk>>>(buf2, W2, nullptr, buf1, M, 256, 512);
    gemm_kernel<1><<<grid(256), blk>>>(adj,  buf1, b2,    buf2, M, 256, M);
    // Layer 3: T = X2 @ W3 ; out = adj @ T + b3
    gemm_kernel<0><<<grid(128), blk>>>(buf2, W3, nullptr, buf1, M, 128, 256);
    gemm_kernel<1><<<grid(128), blk>>>(adj,  buf1, b3,    out,  M, 128, M);
}

// round 4
// speedup vs baseline: 1.0032x; 1.0032x over previous
#include <cuda_runtime.h>
#include <cstdint>

// ---------------------------------------------------------------------------
// GCN1: x3 = adj@( adj@( dropout(relu(adj@(x@W1)+b1)) @ W2 + b2 ) @ W3 ) + b3
// Shapes: x 10000x1024, adj 10000x10000, W1 1024x512, W2 512x256, W3 256x128.
// All fp32 row-major. Dropout mask = JAX *partitionable* threefry2x32,
// key (0,42), p=0.5: per-element 64-bit counter i -> pair (hi=0, lo=i),
// 32-bit draw = out0 ^ out1 (the bit_width==32 branch), keep <=> top bit == 0.
// ---------------------------------------------------------------------------

static __device__ float g_buf1[10000 * 512];
static __device__ float g_buf2[10000 * 512];

__device__ __forceinline__ unsigned rotl32(unsigned v, int s) {
    return (v << s) | (v >> (32 - s));
}

// JAX partitionable threefry2x32, key (0, 42).
// counts = iota(uint64, size); pair = (hi32(i), lo32(i)) = (0, i) for i < 2^32.
// 32-bit draw = out0 ^ out1 ; uniform<0.5  <=>  top bit of draw == 0.
__device__ __forceinline__ bool dropout_keep(unsigned idx) {
    const unsigned ks0 = 0u, ks1 = 42u;
    const unsigned ks2 = 0x1BD11BDAu ^ ks0 ^ ks1;
    unsigned x0 = 0u + ks0;       // counter hi word = 0
    unsigned x1 = idx + ks1;      // counter lo word = idx
#define TF_R(r) { x0 += x1; x1 = rotl32(x1, (r)); x1 ^= x0; }
    TF_R(13) TF_R(15) TF_R(26) TF_R(6)
    x0 += ks1; x1 += ks2 + 1u;
    TF_R(17) TF_R(29) TF_R(16) TF_R(24)
    x0 += ks2; x1 += ks0 + 2u;
    TF_R(13) TF_R(15) TF_R(26) TF_R(6)
    x0 += ks0; x1 += ks1 + 3u;
    TF_R(17) TF_R(29) TF_R(16) TF_R(24)
    x0 += ks1; x1 += ks2 + 4u;
    TF_R(13) TF_R(15) TF_R(26) TF_R(6)
    x0 += ks2; x1 += ks0 + 5u;
#undef TF_R
    return ((x0 ^ x1) & 0x80000000u) == 0u;
}

// ---------------------------------------------------------------------------
// Tiled fp32 GEMM: C[M,N] = A[M,K] @ B[K,N] (+bias) (+relu+dropout)
// BM=128, BN=64, BK=8; 256 threads; 8x4 accumulators per thread.
// Requires: N % 64 == 0, K % 8 == 0 (true for all 6 calls). M guarded.
// EPI: 0 = none, 1 = +bias, 2 = +bias, relu, dropout(threefry)
// ---------------------------------------------------------------------------
constexpr int BM = 128, BN = 64, BK = 8, TM = 8, TN = 4;

template <int EPI>
__global__ __launch_bounds__(256)
void gemm_kernel(const float* __restrict__ A, const float* __restrict__ B,
                 const float* __restrict__ bias, float* __restrict__ C,
                 int M, int N, int K)
{
    __shared__ __align__(16) float As[BK][BM];   // transposed A tile
    __shared__ __align__(16) float Bs[BK][BN];

    const int tid = threadIdx.x;
    const int tx = tid & 15;    // 0..15 -> column group (TN=4 wide)
    const int ty = tid >> 4;    // 0..15 -> row group    (TM=8 tall)
    const int bm0 = blockIdx.y * BM;
    const int bn0 = blockIdx.x * BN;

    // A tile loads: 128x8 = 1024 floats / 256 thr = one float4 each (along K)
    const int aRow = tid >> 1;          // 0..127
    const int aK   = (tid & 1) * 4;     // 0 or 4
    // B tile loads: 8x64 = 512 floats / 256 thr = one float2 each
    const int bRow = tid >> 5;          // 0..7
    const int bCol = (tid & 31) * 2;    // 0..62

    const int gARow = bm0 + aRow;
    const bool aValid = gARow < M;
    const float* Aptr = A + (size_t)gARow * K + aK;
    const float* Bptr = B + (size_t)bRow * N + bn0 + bCol;

    float acc[TM][TN];
#pragma unroll
    for (int i = 0; i < TM; i++)
#pragma unroll
        for (int j = 0; j < TN; j++) acc[i][j] = 0.0f;

    const int numTiles = K / BK;

    float4 aReg = aValid ? *(const float4*)Aptr : make_float4(0.f, 0.f, 0.f, 0.f);
    float2 bReg = *(const float2*)Bptr;

    for (int t = 0; t < numTiles; ++t) {
        As[aK + 0][aRow] = aReg.x;
        As[aK + 1][aRow] = aReg.y;
        As[aK + 2][aRow] = aReg.z;
        As[aK + 3][aRow] = aReg.w;
        Bs[bRow][bCol]     = bReg.x;
        Bs[bRow][bCol + 1] = bReg.y;
        __syncthreads();

        // prefetch next tile into registers while computing this one
        if (t + 1 < numTiles) {
            const float* An = Aptr + (size_t)(t + 1) * BK;
            const float* Bn = Bptr + (size_t)(t + 1) * BK * N;
            aReg = aValid ? *(const float4*)An : make_float4(0.f, 0.f, 0.f, 0.f);
            bReg = *(const float2*)Bn;
        }

#pragma unroll
        for (int kk = 0; kk < BK; ++kk) {
            const float4 a0 = *(const float4*)&As[kk][ty * TM];
            const float4 a1 = *(const float4*)&As[kk][ty * TM + 4];
            const float4 bv = *(const float4*)&Bs[kk][tx * TN];
            const float a[TM] = {a0.x, a0.y, a0.z, a0.w, a1.x, a1.y, a1.z, a1.w};
            const float b[TN] = {bv.x, bv.y, bv.z, bv.w};
#pragma unroll
            for (int i = 0; i < TM; i++)
#pragma unroll
                for (int j = 0; j < TN; j++)
                    acc[i][j] = fmaf(a[i], b[j], acc[i][j]);
        }
        __syncthreads();
    }

    // Epilogue (vectorized float4 column stores; columns contiguous per thread)
    const int c0 = bn0 + tx * TN;
    float4 bias4 = make_float4(0.f, 0.f, 0.f, 0.f);
    if (EPI >= 1) bias4 = *(const float4*)&bias[c0];

#pragma unroll
    for (int i = 0; i < TM; i++) {
        const int r = bm0 + ty * TM + i;
        if (r < M) {
            float v[TN];
#pragma unroll
            for (int j = 0; j < TN; j++) {
                float val = acc[i][j];
                if (EPI >= 1) val += (&bias4.x)[j];
                if (EPI == 2) {
                    val = fmaxf(val, 0.0f);
                    const unsigned idx = (unsigned)r * (unsigned)N + (unsigned)(c0 + j);
                    val = dropout_keep(idx) ? val * 2.0f : 0.0f;
                }
                v[j] = val;
            }
            *(float4*)&C[(size_t)r * N + c0] = make_float4(v[0], v[1], v[2], v[3]);
        }
    }
}

extern "C" void kernel_launch(void* const* d_in, const int* in_sizes, int n_in,
                              void* d_out, int out_size)
{
    const float* x   = (const float*)d_in[0];
    const float* adj = (const float*)d_in[1];
    const float* W1  = (const float*)d_in[2];
    const float* b1  = (const float*)d_in[3];
    const float* W2  = (const float*)d_in[4];
    const float* b2  = (const float*)d_in[5];
    const float* W3  = (const float*)d_in[6];
    const float* b3  = (const float*)d_in[7];
    float* out = (float*)d_out;

    float *buf1, *buf2;
    cudaGetSymbolAddress((void**)&buf1, g_buf1);
    cudaGetSymbolAddress((void**)&buf2, g_buf2);

    const int M = 10000;
    dim3 blk(256);
    auto grid = [&](int N) { return dim3((N + BN - 1) / BN, (M + BM - 1) / BM); };

    // Layer 1: H = x @ W1 ; X1 = dropout(relu(adj @ H + b1))
    gemm_kernel<0><<<grid(512), blk>>>(x,   W1, nullptr, buf1, M, 512, 1024);
    gemm_kernel<2><<<grid(512), blk>>>(adj, buf1, b1,    buf2, M, 512, M);
    // Layer 2: T = X1 @ W2 ; X2 = adj @ T + b2
    gemm_kernel<0><<<grid(256), blk>>>(buf2, W2, nullptr, buf1, M, 256, 512);
    gemm_kernel<1><<<grid(256), blk>>>(adj,  buf1, b2,    buf2, M, 256, M);
    // Layer 3: T = X2 @ W3 ; out = adj @ T + b3
    gemm_kernel<0><<<grid(128), blk>>>(buf2, W3, nullptr, buf1, M, 128, 256);
    gemm_kernel<1><<<grid(128), blk>>>(adj,  buf1, b3,    out,  M, 128, M);
}

// round 6
// speedup vs baseline: 1.5499x; 1.5449x over previous
#include <cuda_runtime.h>
#include <cstdint>

#define MM 10000
static __device__ float g_adj[(size_t)MM * MM];
static __device__ float g_x[(size_t)MM * 1024];
static __device__ float g_w1t[512 * 1024];
static __device__ float g_w2t[256 * 512];
static __device__ float g_w3t[128 * 256];
static __device__ float g_Ht[(size_t)512 * MM];   // transposed intermediates
static __device__ float g_X[(size_t)MM * 512];    // row-major intermediates
static __device__ unsigned g_mask[MM * 512 / 32]; // dropout bitmask

// ------------------------------ helpers -----------------------------------
__device__ __forceinline__ uint32_t smem_u32(const void* p) {
    uint32_t a;
    asm("{ .reg .u64 t; cvta.to.shared.u64 t, %1; cvt.u32.u64 %0, t; }" : "=r"(a) : "l"(p));
    return a;
}
__device__ __forceinline__ float rna_tf32(float x) {
    uint32_t r;
    asm("cvt.rna.tf32.f32 %0, %1;" : "=r"(r) : "f"(x));
    return __uint_as_float(r);
}
__device__ __forceinline__ void cp_async16(uint32_t dst, const float* src, uint32_t sz) {
    asm volatile("cp.async.cg.shared.global [%0], [%1], 16, %2;" :: "r"(dst), "l"(src), "r"(sz) : "memory");
}
__device__ __forceinline__ void cp_commit() { asm volatile("cp.async.commit_group;" ::: "memory"); }
template <int N> __device__ __forceinline__ void cp_wait() {
    asm volatile("cp.async.wait_group %0;" :: "n"(N) : "memory");
}
__device__ __forceinline__ void ldsm4(uint32_t& r0, uint32_t& r1, uint32_t& r2, uint32_t& r3,
                                      uint32_t addr) {
    asm volatile("ldmatrix.sync.aligned.m8n8.x4.shared.b16 {%0,%1,%2,%3}, [%4];"
                 : "=r"(r0), "=r"(r1), "=r"(r2), "=r"(r3) : "r"(addr));
}
__device__ __forceinline__ void mma8(float* c, const uint32_t* a, const uint32_t* b) {
    asm volatile(
        "mma.sync.aligned.m16n8k8.row.col.f32.tf32.tf32.f32 "
        "{%0,%1,%2,%3}, {%4,%5,%6,%7}, {%8,%9}, {%0,%1,%2,%3};"
        : "+f"(c[0]), "+f"(c[1]), "+f"(c[2]), "+f"(c[3])
        : "r"(a[0]), "r"(a[1]), "r"(a[2]), "r"(a[3]), "r"(b[0]), "r"(b[1]));
}

// ----------------------- dropout mask (JAX threefry) -----------------------
__device__ __forceinline__ unsigned rotl32(unsigned v, int s) { return (v << s) | (v >> (32 - s)); }
// partitionable threefry2x32, key (0,42): pair=(0, idx); 32-bit draw = x0^x1.
__device__ __forceinline__ bool dropout_keep(unsigned idx) {
    const unsigned ks1 = 42u, ks2 = 0x1BD11BDAu ^ 42u;
    unsigned x0 = 0u, x1 = idx + ks1;
#define TF_R(r) { x0 += x1; x1 = rotl32(x1, (r)); x1 ^= x0; }
    TF_R(13) TF_R(15) TF_R(26) TF_R(6)  x0 += ks1; x1 += ks2 + 1u;
    TF_R(17) TF_R(29) TF_R(16) TF_R(24) x0 += ks2; x1 += 2u;
    TF_R(13) TF_R(15) TF_R(26) TF_R(6)  x0 += 0u;  x1 += ks1 + 3u;
    TF_R(17) TF_R(29) TF_R(16) TF_R(24) x0 += ks1; x1 += ks2 + 4u;
    TF_R(13) TF_R(15) TF_R(26) TF_R(6)  x0 += ks2; x1 += 5u;
#undef TF_R
    return ((x0 ^ x1) & 0x80000000u) == 0u;
}
__global__ void mask_k(int total) {
    int i = blockIdx.x * blockDim.x + threadIdx.x;
    bool k = (i < total) && dropout_keep((unsigned)i);
    unsigned b = __ballot_sync(0xFFFFFFFF, k);
    if ((threadIdx.x & 31) == 0 && i < total) g_mask[i >> 5] = b;
}

// ------------------------------ prep kernels -------------------------------
__global__ void round_k(const float* __restrict__ in, float* __restrict__ out, int n4) {
    int i = blockIdx.x * blockDim.x + threadIdx.x, st = gridDim.x * blockDim.x;
    for (; i < n4; i += st) {
        float4 v = ((const float4*)in)[i];
        v.x = rna_tf32(v.x); v.y = rna_tf32(v.y); v.z = rna_tf32(v.z); v.w = rna_tf32(v.w);
        ((float4*)out)[i] = v;
    }
}
// W [K,N] row-major -> Wt [N,K] row-major, rounded
__global__ void transpose_k(const float* __restrict__ in, float* __restrict__ out, int K, int N) {
    __shared__ float t[32][33];
    int n0 = blockIdx.x * 32, k0 = blockIdx.y * 32;
    for (int i = 0; i < 32; i += 8) {
        int k = k0 + threadIdx.y + i, n = n0 + threadIdx.x;
        if (k < K && n < N) t[threadIdx.y + i][threadIdx.x] = in[(size_t)k * N + n];
    }
    __syncthreads();
    for (int i = 0; i < 32; i += 8) {
        int n = n0 + threadIdx.y + i, k = k0 + threadIdx.x;
        if (n < N && k < K) out[(size_t)n * K + k] = rna_tf32(t[threadIdx.x][threadIdx.y + i]);
    }
}

// ------------------------------ MMA GEMM -----------------------------------
// C[M,N] = A[M,K] @ Bt[N,K]^T. A row-major, Bt row-major (K contiguous both).
// CTA 128x64, 4 warps (2x2, warp tile 64x32), BK=32, 3-stage cp.async.
// EPI: 0 none | 1 +bias | 2 +bias,relu,dropout.  TRANS: store C^T.  ROUND: tf32 RN.
constexpr int BM = 128, BN = 64, BK = 32, STG = 3;
constexpr int ASZ = BM * BK * 4;            // 16384
constexpr int BSZ = BN * BK * 4;            // 8192
constexpr int SSZ = ASZ + BSZ;              // 24576
constexpr int SMEM_BYTES = SSZ * STG + 1024;

template <int EPI, bool TRANS, bool ROUND>
__global__ void __launch_bounds__(128, 2)
gemm_mma(const float* __restrict__ A, const float* __restrict__ Bt,
         const float* __restrict__ bias, float* __restrict__ C, int M, int N, int K) {
    extern __shared__ char smraw[];
    const uint32_t base = (smem_u32(smraw) + 1023) & ~1023u;

    const int tid = threadIdx.x, lane = tid & 31, wid = tid >> 5;
    const int warpM = wid & 1, warpN = wid >> 1;
    const int m0 = blockIdx.y * BM, n0 = blockIdx.x * BN;
    const int nc = (K + BK - 1) / BK;

    // producer mapping: every thread loads one A row (8x16B); threads 0-63 one B row
    const int aRow = tid;
    const bool aV = (m0 + aRow) < M;
    const float* aSrc = A + (size_t)(m0 + aRow) * K;
    const uint32_t aDst = base + (uint32_t)aRow * 128;
    const int bRow = tid & 63;
    const float* bSrc = Bt + (size_t)(n0 + bRow) * K;
    const uint32_t bDst = base + ASZ + (uint32_t)bRow * 128;
    const bool doB = tid < 64;

    float acc[4][4][4];
#pragma unroll
    for (int a = 0; a < 4; a++)
#pragma unroll
        for (int b = 0; b < 4; b++)
#pragma unroll
            for (int i = 0; i < 4; i++) acc[a][b][i] = 0.0f;

    // ldmatrix per-thread bases
    const uint32_t q = lane & 7;
    const uint32_t hA = lane >> 4;                 // A group select
    const uint32_t hB = (lane >> 3) & 1;           // B group select
    const uint32_t aF = base + (uint32_t)(warpM * 64 + (lane & 15)) * 128;
    const uint32_t bF = base + ASZ + (uint32_t)(warpN * 32 + ((lane >> 4) << 3) + (lane & 7)) * 128;

    auto load_chunk = [&](int c, int s) {
        const int k0 = c * BK, kRem = K - k0;
        const uint32_t sb = (uint32_t)s * SSZ;
#pragma unroll
        for (int g = 0; g < 8; g++)
            cp_async16(aDst + sb + (uint32_t)((g ^ (aRow & 7)) << 4), aSrc + k0 + g * 4,
                       (aV && g * 4 < kRem) ? 16u : 0u);
        if (doB) {
#pragma unroll
            for (int g = 0; g < 8; g++)
                cp_async16(bDst + sb + (uint32_t)((g ^ (bRow & 7)) << 4), bSrc + k0 + g * 4,
                           (g * 4 < kRem) ? 16u : 0u);
        }
    };

    for (int s = 0; s < STG - 1; s++) {
        if (s < nc) load_chunk(s, s);
        cp_commit();
    }

    for (int c = 0; c < nc; c++) {
        if (c + STG - 1 < nc) load_chunk(c + STG - 1, (c + STG - 1) % STG);
        cp_commit();
        cp_wait<STG - 1>();
        __syncthreads();
        const uint32_t sb = (uint32_t)(c % STG) * SSZ;
#pragma unroll
        for (int ks = 0; ks < 4; ks++) {
            uint32_t afr[4][4], bfr[4][2];
#pragma unroll
            for (int mt = 0; mt < 4; mt++)
                ldsm4(afr[mt][0], afr[mt][1], afr[mt][2], afr[mt][3],
                      aF + sb + (uint32_t)(mt * 2048) + ((((uint32_t)ks * 2 + hA) ^ q) << 4));
#pragma unroll
            for (int np = 0; np < 2; np++) {
                uint32_t r0, r1, r2, r3;
                ldsm4(r0, r1, r2, r3,
                      bF + sb + (uint32_t)(np * 2048) + ((((uint32_t)ks * 2 + hB) ^ q) << 4));
                bfr[np * 2][0] = r0; bfr[np * 2][1] = r1;
                bfr[np * 2 + 1][0] = r2; bfr[np * 2 + 1][1] = r3;
            }
#pragma unroll
            for (int mt = 0; mt < 4; mt++)
#pragma unroll
                for (int nt = 0; nt < 4; nt++)
                    mma8(acc[mt][nt], afr[mt], bfr[nt]);
        }
        __syncthreads();
    }

    // ---------------- epilogue ----------------
    const int rBase = m0 + warpM * 64 + (lane >> 2);
    const int cBase = n0 + warpN * 32 + (lane & 3) * 2;
#pragma unroll
    for (int mt = 0; mt < 4; mt++) {
#pragma unroll
        for (int hf = 0; hf < 2; hf++) {
            const int r = rBase + mt * 16 + hf * 8;
            if (r < M) {
#pragma unroll
                for (int nt = 0; nt < 4; nt++) {
                    const int cc = cBase + nt * 8;
                    float v0 = acc[mt][nt][hf * 2 + 0];
                    float v1 = acc[mt][nt][hf * 2 + 1];
                    if (EPI >= 1) { v0 += bias[cc]; v1 += bias[cc + 1]; }
                    if (EPI == 2) {
                        v0 = fmaxf(v0, 0.0f); v1 = fmaxf(v1, 0.0f);
                        const unsigned i0 = (unsigned)r * (unsigned)N + (unsigned)cc;
                        v0 = ((g_mask[i0 >> 5] >> (i0 & 31)) & 1u) ? v0 * 2.0f : 0.0f;
                        const unsigned i1 = i0 + 1;
                        v1 = ((g_mask[i1 >> 5] >> (i1 & 31)) & 1u) ? v1 * 2.0f : 0.0f;
                    }
                    if (ROUND) { v0 = rna_tf32(v0); v1 = rna_tf32(v1); }
                    if (TRANS) {
                        C[(size_t)cc * M + r] = v0;
                        C[(size_t)(cc + 1) * M + r] = v1;
                    } else {
                        *(float2*)&C[(size_t)r * N + cc] = make_float2(v0, v1);
                    }
                }
            }
        }
    }
}

// ------------------------------ launch -------------------------------------
extern "C" void kernel_launch(void* const* d_in, const int* in_sizes, int n_in,
                              void* d_out, int out_size) {
    const float* x   = (const float*)d_in[0];
    const float* adj = (const float*)d_in[1];
    const float* W1  = (const float*)d_in[2];
    const float* b1  = (const float*)d_in[3];
    const float* W2  = (const float*)d_in[4];
    const float* b2  = (const float*)d_in[5];
    const float* W3  = (const float*)d_in[6];
    const float* b3  = (const float*)d_in[7];
    float* out = (float*)d_out;

    float *adjR, *xR, *w1t, *w2t, *w3t, *Ht, *X;
    cudaGetSymbolAddress((void**)&adjR, g_adj);
    cudaGetSymbolAddress((void**)&xR, g_x);
    cudaGetSymbolAddress((void**)&w1t, g_w1t);
    cudaGetSymbolAddress((void**)&w2t, g_w2t);
    cudaGetSymbolAddress((void**)&w3t, g_w3t);
    cudaGetSymbolAddress((void**)&Ht, g_Ht);
    cudaGetSymbolAddress((void**)&X, g_X);

    const int M = MM, MT = (M + BM - 1) / BM;  // 79

    cudaFuncSetAttribute(gemm_mma<0, true, true>,  cudaFuncAttributeMaxDynamicSharedMemorySize, SMEM_BYTES);
    cudaFuncSetAttribute(gemm_mma<2, false, true>, cudaFuncAttributeMaxDynamicSharedMemorySize, SMEM_BYTES);
    cudaFuncSetAttribute(gemm_mma<1, false, true>, cudaFuncAttributeMaxDynamicSharedMemorySize, SMEM_BYTES);
    cudaFuncSetAttribute(gemm_mma<1, false, false>, cudaFuncAttributeMaxDynamicSharedMemorySize, SMEM_BYTES);

    // prep: round inputs to tf32 (RN), transpose+round weights, dropout bitmask
    round_k<<<4096, 256>>>(adj, adjR, M * (M / 4));
    round_k<<<4096, 256>>>(x, xR, M * 256);
    transpose_k<<<dim3(16, 32), dim3(32, 8)>>>(W1, w1t, 1024, 512);
    transpose_k<<<dim3(8, 16), dim3(32, 8)>>>(W2, w2t, 512, 256);
    transpose_k<<<dim3(4, 8), dim3(32, 8)>>>(W3, w3t, 256, 128);
    mask_k<<<(M * 512) / 256, 256>>>(M * 512);

    dim3 blk(128);
    // L1: H1t = (x@W1)^T ; X1 = dropout(relu(adj@H1 + b1))
    gemm_mma<0, true, true><<<dim3(8, MT), blk, SMEM_BYTES>>>(xR, w1t, nullptr, Ht, M, 512, 1024);
    gemm_mma<2, false, true><<<dim3(8, MT), blk, SMEM_BYTES>>>(adjR, Ht, b1, X, M, 512, M);
    // L2: H2t = (X1@W2)^T ; X2 = adj@H2 + b2
    gemm_mma<0, true, true><<<dim3(4, MT), blk, SMEM_BYTES>>>(X, w2t, nullptr, Ht, M, 256, 512);
    gemm_mma<1, false, true><<<dim3(4, MT), blk, SMEM_BYTES>>>(adjR, Ht, b2, X, M, 256, M);
    // L3: H3t = (X2@W3)^T ; out = adj@H3 + b3
    gemm_mma<0, true, true><<<dim3(2, MT), blk, SMEM_BYTES>>>(X, w3t, nullptr, Ht, M, 128, 256);
    gemm_mma<1, false, false><<<dim3(2, MT), blk, SMEM_BYTES>>>(adjR, Ht, b3, out, M, 128, M);
}

// round 8
// speedup vs baseline: 3.5162x; 2.2687x over previous
#include <cuda_runtime.h>
#include <cuda_fp16.h>
#include <cstdint>

#define MM 10000
static __device__ unsigned short g_adj_h[(size_t)MM * MM];   // adj as fp16 (200MB)
static __device__ unsigned short g_x_h[(size_t)MM * 1024];
static __device__ unsigned short g_w1t[512 * 1024];
static __device__ unsigned short g_w2t[256 * 512];
static __device__ unsigned short g_w3t[128 * 256];
static __device__ unsigned short g_Ht[(size_t)512 * MM];     // transposed feature outputs
static __device__ unsigned short g_X[(size_t)MM * 512];      // row-major intermediates
static __device__ float g_P[(size_t)2 * MM * 512];           // split-K fp32 partials
static __device__ unsigned g_mask[MM * 512 / 32];            // dropout bitmask

// X2 is stored scaled by 1/64 in fp16 (its column-mean component reaches ~2e5
// via the adj mean-amplification path and would overflow fp16); the final
// combine multiplies the partials by 64 before adding b3. Power-of-2 => exact.
#define X2_INV_SCALE 0.015625f
#define X2_SCALE 64.0f

// ------------------------------ helpers -----------------------------------
__device__ __forceinline__ uint32_t smem_u32(const void* p) {
    uint32_t a;
    asm("{ .reg .u64 t; cvta.to.shared.u64 t, %1; cvt.u32.u64 %0, t; }" : "=r"(a) : "l"(p));
    return a;
}
__device__ __forceinline__ void cp_async16(uint32_t dst, const void* src, uint32_t sz) {
    asm volatile("cp.async.cg.shared.global [%0], [%1], 16, %2;" :: "r"(dst), "l"(src), "r"(sz) : "memory");
}
__device__ __forceinline__ void cp_commit() { asm volatile("cp.async.commit_group;" ::: "memory"); }
template <int N> __device__ __forceinline__ void cp_wait() {
    asm volatile("cp.async.wait_group %0;" :: "n"(N) : "memory");
}
__device__ __forceinline__ void ldsm4(uint32_t& r0, uint32_t& r1, uint32_t& r2, uint32_t& r3,
                                      uint32_t addr) {
    asm volatile("ldmatrix.sync.aligned.m8n8.x4.shared.b16 {%0,%1,%2,%3}, [%4];"
                 : "=r"(r0), "=r"(r1), "=r"(r2), "=r"(r3) : "r"(addr));
}
__device__ __forceinline__ void mma16(float* c, const uint32_t* a, const uint32_t* b) {
    asm volatile(
        "mma.sync.aligned.m16n8k16.row.col.f32.f16.f16.f32 "
        "{%0,%1,%2,%3}, {%4,%5,%6,%7}, {%8,%9}, {%0,%1,%2,%3};"
        : "+f"(c[0]), "+f"(c[1]), "+f"(c[2]), "+f"(c[3])
        : "r"(a[0]), "r"(a[1]), "r"(a[2]), "r"(a[3]), "r"(b[0]), "r"(b[1]));
}

// ----------------------- dropout mask (JAX threefry) -----------------------
__device__ __forceinline__ unsigned rotl32(unsigned v, int s) { return (v << s) | (v >> (32 - s)); }
__device__ __forceinline__ bool dropout_keep(unsigned idx) {
    const unsigned ks1 = 42u, ks2 = 0x1BD11BDAu ^ 42u;
    unsigned x0 = 0u, x1 = idx + ks1;
#define TF_R(r) { x0 += x1; x1 = rotl32(x1, (r)); x1 ^= x0; }
    TF_R(13) TF_R(15) TF_R(26) TF_R(6)  x0 += ks1; x1 += ks2 + 1u;
    TF_R(17) TF_R(29) TF_R(16) TF_R(24) x0 += ks2; x1 += 2u;
    TF_R(13) TF_R(15) TF_R(26) TF_R(6)  x0 += 0u;  x1 += ks1 + 3u;
    TF_R(17) TF_R(29) TF_R(16) TF_R(24) x0 += ks1; x1 += ks2 + 4u;
    TF_R(13) TF_R(15) TF_R(26) TF_R(6)  x0 += ks2; x1 += 5u;
#undef TF_R
    return ((x0 ^ x1) & 0x80000000u) == 0u;
}
__global__ void mask_k(int total) {
    int i = blockIdx.x * blockDim.x + threadIdx.x;
    bool k = (i < total) && dropout_keep((unsigned)i);
    unsigned b = __ballot_sync(0xFFFFFFFF, k);
    if ((threadIdx.x & 31) == 0 && i < total) g_mask[i >> 5] = b;
}

// ------------------------------ prep kernels -------------------------------
__global__ void tohalf_k(const float* __restrict__ in, __half2* __restrict__ out, int n4) {
    int i = blockIdx.x * blockDim.x + threadIdx.x, st = gridDim.x * blockDim.x;
    for (; i < n4; i += st) {
        float4 v = ((const float4*)in)[i];
        out[2 * i]     = __floats2half2_rn(v.x, v.y);
        out[2 * i + 1] = __floats2half2_rn(v.z, v.w);
    }
}
// W [K,N] fp32 row-major -> Wt [N,K] fp16 row-major
__global__ void transpose_k(const float* __restrict__ in, __half* __restrict__ out, int K, int N) {
    __shared__ float t[32][33];
    int n0 = blockIdx.x * 32, k0 = blockIdx.y * 32;
    for (int i = 0; i < 32; i += 8) {
        int k = k0 + threadIdx.y + i, n = n0 + threadIdx.x;
        if (k < K && n < N) t[threadIdx.y + i][threadIdx.x] = in[(size_t)k * N + n];
    }
    __syncthreads();
    for (int i = 0; i < 32; i += 8) {
        int n = n0 + threadIdx.y + i, k = k0 + threadIdx.x;
        if (n < N && k < K) out[(size_t)n * K + k] = __float2half_rn(t[threadIdx.x][threadIdx.y + i]);
    }
}

// ------------------------------ fp16 MMA GEMM ------------------------------
// C = A[M,Kstride] @ Bt[N,Kstride]^T over K range [z*kLen, (z+1)*kLen).
// CTA 128x64, 4 warps (2x2), BK=64 halves, 3-stage cp.async.
// TRANS: store C^T as fp16 (raw accumulator). Else: fp32 partial to slab z.
constexpr int BM = 128, BN = 64, BK = 64, STG = 3;
constexpr int ASZ = BM * 128, BSZ = BN * 128, SSZ = ASZ + BSZ;   // 16K + 8K
constexpr int SMEM_BYTES = SSZ * STG + 1024;                      // 74752

template <bool TRANS>
__global__ void __launch_bounds__(128, 2)
gemm_h(const __half* __restrict__ A, const __half* __restrict__ Bt,
       void* __restrict__ Cv, int M, int N, int Kstride, int kLen) {
    extern __shared__ char smraw[];
    const uint32_t base = (smem_u32(smraw) + 1023) & ~1023u;

    const int tid = threadIdx.x, lane = tid & 31, wid = tid >> 5;
    const int warpM = wid & 1, warpN = wid >> 1;
    const int m0 = blockIdx.y * BM, n0 = blockIdx.x * BN;
    const int kOff = blockIdx.z * kLen;
    const int nc = (kLen + BK - 1) / BK;

    const int aRow = tid;
    const bool aV = (m0 + aRow) < M;
    const __half* aSrc = A + (size_t)(m0 + aRow) * Kstride + kOff;
    const uint32_t aDst = base + (uint32_t)aRow * 128;
    const int bRow = tid & 63;
    const __half* bSrc = Bt + (size_t)(n0 + bRow) * Kstride + kOff;
    const uint32_t bDst = base + ASZ + (uint32_t)bRow * 128;
    const bool doB = tid < 64;

    float acc[4][4][4];
#pragma unroll
    for (int a = 0; a < 4; a++)
#pragma unroll
        for (int b = 0; b < 4; b++)
#pragma unroll
            for (int i = 0; i < 4; i++) acc[a][b][i] = 0.0f;

    const uint32_t q = lane & 7;
    const uint32_t hA = lane >> 4;
    const uint32_t hB = (lane >> 3) & 1;
    const uint32_t aF = base + (uint32_t)(warpM * 64 + (lane & 15)) * 128;
    const uint32_t bF = base + ASZ + (uint32_t)(warpN * 32 + ((lane >> 4) << 3) + (lane & 7)) * 128;

    auto load_chunk = [&](int c, int s) {
        const int k0 = c * BK, kRem = kLen - k0;
        const uint32_t sb = (uint32_t)s * SSZ;
#pragma unroll
        for (int g = 0; g < 8; g++)
            cp_async16(aDst + sb + (uint32_t)((g ^ (aRow & 7)) << 4), aSrc + k0 + g * 8,
                       (aV && g * 8 < kRem) ? 16u : 0u);
        if (doB) {
#pragma unroll
            for (int g = 0; g < 8; g++)
                cp_async16(bDst + sb + (uint32_t)((g ^ (bRow & 7)) << 4), bSrc + k0 + g * 8,
                           (g * 8 < kRem) ? 16u : 0u);
        }
    };

    for (int s = 0; s < STG - 1; s++) {
        if (s < nc) load_chunk(s, s);
        cp_commit();
    }

    for (int c = 0; c < nc; c++) {
        if (c + STG - 1 < nc) load_chunk(c + STG - 1, (c + STG - 1) % STG);
        cp_commit();
        cp_wait<STG - 1>();
        __syncthreads();
        const uint32_t sb = (uint32_t)(c % STG) * SSZ;
#pragma unroll
        for (int ks = 0; ks < 4; ks++) {
            uint32_t afr[4][4], bfr[4][2];
#pragma unroll
            for (int mt = 0; mt < 4; mt++)
                ldsm4(afr[mt][0], afr[mt][1], afr[mt][2], afr[mt][3],
                      aF + sb + (uint32_t)(mt * 2048) + ((((uint32_t)ks * 2 + hA) ^ q) << 4));
#pragma unroll
            for (int np = 0; np < 2; np++) {
                uint32_t r0, r1, r2, r3;
                ldsm4(r0, r1, r2, r3,
                      bF + sb + (uint32_t)(np * 2048) + ((((uint32_t)ks * 2 + hB) ^ q) << 4));
                bfr[np * 2][0] = r0;     bfr[np * 2][1] = r1;
                bfr[np * 2 + 1][0] = r2; bfr[np * 2 + 1][1] = r3;
            }
#pragma unroll
            for (int mt = 0; mt < 4; mt++)
#pragma unroll
                for (int nt = 0; nt < 4; nt++)
                    mma16(acc[mt][nt], afr[mt], bfr[nt]);
        }
        __syncthreads();
    }

    // ---------------- epilogue ----------------
    const int rBase = m0 + warpM * 64 + (lane >> 2);
    const int cBase = n0 + warpN * 32 + (lane & 3) * 2;
#pragma unroll
    for (int mt = 0; mt < 4; mt++) {
#pragma unroll
        for (int hf = 0; hf < 2; hf++) {
            const int r = rBase + mt * 16 + hf * 8;
            if (r < M) {
#pragma unroll
                for (int nt = 0; nt < 4; nt++) {
                    const int cc = cBase + nt * 8;
                    const float v0 = acc[mt][nt][hf * 2 + 0];
                    const float v1 = acc[mt][nt][hf * 2 + 1];
                    if (TRANS) {
                        __half* C = (__half*)Cv;
                        C[(size_t)cc * M + r] = __float2half_rn(v0);
                        C[(size_t)(cc + 1) * M + r] = __float2half_rn(v1);
                    } else {
                        float* C = (float*)Cv + (size_t)blockIdx.z * M * N;
                        *(float2*)&C[(size_t)r * N + cc] = make_float2(v0, v1);
                    }
                }
            }
        }
    }
}

// --------------------- split-K combine + layer epilogue --------------------
// MODE 1: bias,relu,dropout -> half
// MODE 2: bias, scale by 1/64 -> half   (X2; avoids fp16 overflow)
// MODE 3: unscale by 64, bias -> fp32   (final output)
template <int MODE>
__global__ void combine_k(const float* __restrict__ P, const float* __restrict__ bias,
                          void* __restrict__ out, int Mn, int N) {
    int i = blockIdx.x * blockDim.x + threadIdx.x;
    if (i >= Mn) return;
    if (MODE == 1) {
        float v = P[i] + P[Mn + i] + bias[i % N];
        v = fmaxf(v, 0.0f);
        v = ((g_mask[i >> 5] >> (i & 31)) & 1u) ? v * 2.0f : 0.0f;
        ((__half*)out)[i] = __float2half_rn(v);
    } else if (MODE == 2) {
        float v = P[i] + P[Mn + i] + bias[i % N];
        ((__half*)out)[i] = __float2half_rn(v * X2_INV_SCALE);
    } else {
        float v = (P[i] + P[Mn + i]) * X2_SCALE + bias[i % N];
        ((float*)out)[i] = v;
    }
}

// ------------------------------ launch -------------------------------------
extern "C" void kernel_launch(void* const* d_in, const int* in_sizes, int n_in,
                              void* d_out, int out_size) {
    const float* x   = (const float*)d_in[0];
    const float* adj = (const float*)d_in[1];
    const float* W1  = (const float*)d_in[2];
    const float* b1  = (const float*)d_in[3];
    const float* W2  = (const float*)d_in[4];
    const float* b2  = (const float*)d_in[5];
    const float* W3  = (const float*)d_in[6];
    const float* b3  = (const float*)d_in[7];
    float* out = (float*)d_out;

    __half *adjH, *xH, *w1t, *w2t, *w3t, *Ht, *X;
    float* P;
    cudaGetSymbolAddress((void**)&adjH, g_adj_h);
    cudaGetSymbolAddress((void**)&xH, g_x_h);
    cudaGetSymbolAddress((void**)&w1t, g_w1t);
    cudaGetSymbolAddress((void**)&w2t, g_w2t);
    cudaGetSymbolAddress((void**)&w3t, g_w3t);
    cudaGetSymbolAddress((void**)&Ht, g_Ht);
    cudaGetSymbolAddress((void**)&X, g_X);
    cudaGetSymbolAddress((void**)&P, g_P);

    const int M = MM, MT = (M + BM - 1) / BM;  // 79
    cudaFuncSetAttribute(gemm_h<true>,  cudaFuncAttributeMaxDynamicSharedMemorySize, SMEM_BYTES);
    cudaFuncSetAttribute(gemm_h<false>, cudaFuncAttributeMaxDynamicSharedMemorySize, SMEM_BYTES);

    dim3 blk(128);
    // launch order chosen so ncu (-s 5 -c 1) profiles the L1 adj GEMM (index 5)
    tohalf_k<<<4096, 256>>>(adj, (__half2*)adjH, M * (M / 4));                 // 0
    mask_k<<<(M * 512) / 256, 256>>>(M * 512);                                // 1
    tohalf_k<<<2048, 256>>>(x, (__half2*)xH, M * 256);                        // 2
    transpose_k<<<dim3(16, 32), dim3(32, 8)>>>(W1, w1t, 1024, 512);           // 3
    // L1: H1t = (x@W1)^T ; P = adj@H1 (split-K) ; X1 = drop(relu(P+b1))
    gemm_h<true><<<dim3(8, MT, 1), blk, SMEM_BYTES>>>(xH, w1t, Ht, M, 512, 1024, 1024);   // 4
    gemm_h<false><<<dim3(8, MT, 2), blk, SMEM_BYTES>>>(adjH, Ht, P, M, 512, M, 5000);     // 5 <- ncu
    combine_k<1><<<(M * 512 + 255) / 256, 256>>>(P, b1, X, M * 512, 512);     // 6
    // L2: H2t = (X1@W2)^T ; X2 = (adj@H2 + b2)/64 stored fp16
    transpose_k<<<dim3(8, 16), dim3(32, 8)>>>(W2, w2t, 512, 256);             // 7
    gemm_h<true><<<dim3(4, MT, 1), blk, SMEM_BYTES>>>(X, w2t, Ht, M, 256, 512, 512);      // 8
    gemm_h<false><<<dim3(4, MT, 2), blk, SMEM_BYTES>>>(adjH, Ht, P, M, 256, M, 5000);     // 9
    combine_k<2><<<(M * 256 + 255) / 256, 256>>>(P, b2, X, M * 256, 256);     // 10
    // L3: H3t = ((X2/64)@W3)^T ; out = 64*(adj@H3) + b3
    transpose_k<<<dim3(4, 8), dim3(32, 8)>>>(W3, w3t, 256, 128);              // 11
    gemm_h<true><<<dim3(2, MT, 1), blk, SMEM_BYTES>>>(X, w3t, Ht, M, 128, 256, 256);      // 12
    gemm_h<false><<<dim3(2, MT, 2), blk, SMEM_BYTES>>>(adjH, Ht, P, M, 128, M, 5000);     // 13
    combine_k<3><<<(M * 128 + 255) / 256, 256>>>(P, b3, out, M * 128, 128);   // 14
}

// round 10
// speedup vs baseline: 4.5490x; 1.2937x over previous
#include <cuda_runtime.h>
#include <cuda_fp16.h>
#include <cstdint>

#define MM 10000
static __device__ unsigned short g_adj_h[(size_t)MM * MM];   // adj as fp16 (200MB)
static __device__ unsigned short g_x_h[(size_t)MM * 1024];
static __device__ unsigned short g_w1t[512 * 1024];
static __device__ unsigned short g_w2t[256 * 512];
static __device__ unsigned short g_w3t[128 * 256];
static __device__ unsigned short g_Ht[(size_t)512 * MM];     // transposed feature outputs
static __device__ unsigned short g_X[(size_t)MM * 512];      // row-major intermediates
static __device__ float g_P[(size_t)2 * MM * 512];           // split-K fp32 partials (10.24M f)
static __device__ unsigned g_mask[MM * 512 / 32];            // dropout bitmask

// X2 stored scaled by 1/64 in fp16 (column-mean amplification through adj
// reaches ~2e5, over fp16 max); final combine un-scales by 64. Exact (pow2).
#define X2_INV_SCALE 0.015625f
#define X2_SCALE 64.0f

// ------------------------------ helpers -----------------------------------
__device__ __forceinline__ uint32_t smem_u32(const void* p) {
    uint32_t a;
    asm("{ .reg .u64 t; cvta.to.shared.u64 t, %1; cvt.u32.u64 %0, t; }" : "=r"(a) : "l"(p));
    return a;
}
__device__ __forceinline__ void cp_async16(uint32_t dst, const void* src, uint32_t sz) {
    asm volatile("cp.async.cg.shared.global [%0], [%1], 16, %2;" :: "r"(dst), "l"(src), "r"(sz) : "memory");
}
__device__ __forceinline__ void cp_commit() { asm volatile("cp.async.commit_group;" ::: "memory"); }
template <int N> __device__ __forceinline__ void cp_wait() {
    asm volatile("cp.async.wait_group %0;" :: "n"(N) : "memory");
}
__device__ __forceinline__ void ldsm4(uint32_t& r0, uint32_t& r1, uint32_t& r2, uint32_t& r3,
                                      uint32_t addr) {
    asm volatile("ldmatrix.sync.aligned.m8n8.x4.shared.b16 {%0,%1,%2,%3}, [%4];"
                 : "=r"(r0), "=r"(r1), "=r"(r2), "=r"(r3) : "r"(addr));
}
__device__ __forceinline__ void mma16(float* c, const uint32_t* a, const uint32_t* b) {
    asm volatile(
        "mma.sync.aligned.m16n8k16.row.col.f32.f16.f16.f32 "
        "{%0,%1,%2,%3}, {%4,%5,%6,%7}, {%8,%9}, {%0,%1,%2,%3};"
        : "+f"(c[0]), "+f"(c[1]), "+f"(c[2]), "+f"(c[3])
        : "r"(a[0]), "r"(a[1]), "r"(a[2]), "r"(a[3]), "r"(b[0]), "r"(b[1]));
}

// ----------------------- dropout mask (JAX threefry) -----------------------
__device__ __forceinline__ unsigned rotl32(unsigned v, int s) { return (v << s) | (v >> (32 - s)); }
__device__ __forceinline__ bool dropout_keep(unsigned idx) {
    const unsigned ks1 = 42u, ks2 = 0x1BD11BDAu ^ 42u;
    unsigned x0 = 0u, x1 = idx + ks1;
#define TF_R(r) { x0 += x1; x1 = rotl32(x1, (r)); x1 ^= x0; }
    TF_R(13) TF_R(15) TF_R(26) TF_R(6)  x0 += ks1; x1 += ks2 + 1u;
    TF_R(17) TF_R(29) TF_R(16) TF_R(24) x0 += ks2; x1 += 2u;
    TF_R(13) TF_R(15) TF_R(26) TF_R(6)  x0 += 0u;  x1 += ks1 + 3u;
    TF_R(17) TF_R(29) TF_R(16) TF_R(24) x0 += ks1; x1 += ks2 + 4u;
    TF_R(13) TF_R(15) TF_R(26) TF_R(6)  x0 += ks2; x1 += 5u;
#undef TF_R
    return ((x0 ^ x1) & 0x80000000u) == 0u;
}
__global__ void mask_k(int total) {
    int i = blockIdx.x * blockDim.x + threadIdx.x;
    bool k = (i < total) && dropout_keep((unsigned)i);
    unsigned b = __ballot_sync(0xFFFFFFFF, k);
    if ((threadIdx.x & 31) == 0 && i < total) g_mask[i >> 5] = b;
}

// ------------------------------ prep kernels -------------------------------
__global__ void tohalf_k(const float* __restrict__ in, __half2* __restrict__ out, int n4) {
    int i = blockIdx.x * blockDim.x + threadIdx.x, st = gridDim.x * blockDim.x;
    for (; i < n4; i += st) {
        float4 v = ((const float4*)in)[i];
        out[2 * i]     = __floats2half2_rn(v.x, v.y);
        out[2 * i + 1] = __floats2half2_rn(v.z, v.w);
    }
}
// W [K,N] fp32 row-major -> Wt [N,K] fp16 row-major
__global__ void transpose_k(const float* __restrict__ in, __half* __restrict__ out, int K, int N) {
    __shared__ float t[32][33];
    int n0 = blockIdx.x * 32, k0 = blockIdx.y * 32;
    for (int i = 0; i < 32; i += 8) {
        int k = k0 + threadIdx.y + i, n = n0 + threadIdx.x;
        if (k < K && n < N) t[threadIdx.y + i][threadIdx.x] = in[(size_t)k * N + n];
    }
    __syncthreads();
    for (int i = 0; i < 32; i += 8) {
        int n = n0 + threadIdx.y + i, k = k0 + threadIdx.x;
        if (n < N && k < K) out[(size_t)n * K + k] = __float2half_rn(t[threadIdx.x][threadIdx.y + i]);
    }
}

// ------------------------------ fp16 MMA GEMM ------------------------------
// C = A[M,Kstride] @ Bt[N,Kstride]^T over K range [z*kLen, min((z+1)*kLen, K)).
// kLen MUST be a multiple of 8 halves so z*kLen is 16B-aligned (cp.async).
// CTA 128x64, 4 warps (2x2), BK=64 halves, 3-stage cp.async, 3 CTAs/SM.
// TRANS: store C^T as fp16 (raw accumulator). Else: fp32 partial to slab z.
constexpr int BM = 128, BN = 64, BK = 64, STG = 3;
constexpr int ASZ = BM * 128, BSZ = BN * 128, SSZ = ASZ + BSZ;   // 16K + 8K
constexpr int SMEM_BYTES = SSZ * STG + 1024;                      // 74752; x3 = 224KB/SM

template <bool TRANS>
__global__ void __launch_bounds__(128, 3)
gemm_h(const __half* __restrict__ A, const __half* __restrict__ Bt,
       void* __restrict__ Cv, int M, int N, int Kstride, int kLen) {
    extern __shared__ char smraw[];
    const uint32_t base = (smem_u32(smraw) + 1023) & ~1023u;

    const int tid = threadIdx.x, lane = tid & 31, wid = tid >> 5;
    const int warpM = wid & 1, warpN = wid >> 1;
    const int m0 = blockIdx.y * BM, n0 = blockIdx.x * BN;
    const int kOff = blockIdx.z * kLen;
    int kl = Kstride - kOff;                 // clamp last split
    if (kl > kLen) kl = kLen;
    const int nc = (kl + BK - 1) / BK;

    const int aRow = tid;
    const bool aV = (m0 + aRow) < M;
    const __half* aSrc = A + (size_t)(m0 + aRow) * Kstride + kOff;
    const uint32_t aDst = base + (uint32_t)aRow * 128;
    const int bRow = tid & 63;
    const __half* bSrc = Bt + (size_t)(n0 + bRow) * Kstride + kOff;
    const uint32_t bDst = base + ASZ + (uint32_t)bRow * 128;
    const bool doB = tid < 64;

    float acc[4][4][4];
#pragma unroll
    for (int a = 0; a < 4; a++)
#pragma unroll
        for (int b = 0; b < 4; b++)
#pragma unroll
            for (int i = 0; i < 4; i++) acc[a][b][i] = 0.0f;

    const uint32_t q = lane & 7;
    const uint32_t hA = lane >> 4;
    const uint32_t hB = (lane >> 3) & 1;
    const uint32_t aF = base + (uint32_t)(warpM * 64 + (lane & 15)) * 128;
    const uint32_t bF = base + ASZ + (uint32_t)(warpN * 32 + ((lane >> 4) << 3) + (lane & 7)) * 128;

    auto load_chunk = [&](int c, int s) {
        const int k0 = c * BK, kRem = kl - k0;
        const uint32_t sb = (uint32_t)s * SSZ;
#pragma unroll
        for (int g = 0; g < 8; g++)
            cp_async16(aDst + sb + (uint32_t)((g ^ (aRow & 7)) << 4), aSrc + k0 + g * 8,
                       (aV && g * 8 < kRem) ? 16u : 0u);
        if (doB) {
#pragma unroll
            for (int g = 0; g < 8; g++)
                cp_async16(bDst + sb + (uint32_t)((g ^ (bRow & 7)) << 4), bSrc + k0 + g * 8,
                           (g * 8 < kRem) ? 16u : 0u);
        }
    };

    for (int s = 0; s < STG - 1; s++) {
        if (s < nc) load_chunk(s, s);
        cp_commit();
    }

    for (int c = 0; c < nc; c++) {
        if (c + STG - 1 < nc) load_chunk(c + STG - 1, (c + STG - 1) % STG);
        cp_commit();
        cp_wait<STG - 1>();
        __syncthreads();
        const uint32_t sb = (uint32_t)(c % STG) * SSZ;
#pragma unroll
        for (int ks = 0; ks < 4; ks++) {
            uint32_t afr[4][4], bfr[4][2];
#pragma unroll
            for (int mt = 0; mt < 4; mt++)
                ldsm4(afr[mt][0], afr[mt][1], afr[mt][2], afr[mt][3],
                      aF + sb + (uint32_t)(mt * 2048) + ((((uint32_t)ks * 2 + hA) ^ q) << 4));
#pragma unroll
            for (int np = 0; np < 2; np++) {
                uint32_t r0, r1, r2, r3;
                ldsm4(r0, r1, r2, r3,
                      bF + sb + (uint32_t)(np * 2048) + ((((uint32_t)ks * 2 + hB) ^ q) << 4));
                bfr[np * 2][0] = r0;     bfr[np * 2][1] = r1;
                bfr[np * 2 + 1][0] = r2; bfr[np * 2 + 1][1] = r3;
            }
#pragma unroll
            for (int mt = 0; mt < 4; mt++)
#pragma unroll
                for (int nt = 0; nt < 4; nt++)
                    mma16(acc[mt][nt], afr[mt], bfr[nt]);
        }
        __syncthreads();
    }

    // ---------------- epilogue ----------------
    const int rBase = m0 + warpM * 64 + (lane >> 2);
    const int cBase = n0 + warpN * 32 + (lane & 3) * 2;
#pragma unroll
    for (int mt = 0; mt < 4; mt++) {
#pragma unroll
        for (int hf = 0; hf < 2; hf++) {
            const int r = rBase + mt * 16 + hf * 8;
            if (r < M) {
#pragma unroll
                for (int nt = 0; nt < 4; nt++) {
                    const int cc = cBase + nt * 8;
                    const float v0 = acc[mt][nt][hf * 2 + 0];
                    const float v1 = acc[mt][nt][hf * 2 + 1];
                    if (TRANS) {
                        __half* C = (__half*)Cv;
                        C[(size_t)cc * M + r] = __float2half_rn(v0);
                        C[(size_t)(cc + 1) * M + r] = __float2half_rn(v1);
                    } else {
                        float* C = (float*)Cv + (size_t)blockIdx.z * M * N;
                        *(float2*)&C[(size_t)r * N + cc] = make_float2(v0, v1);
                    }
                }
            }
        }
    }
}

// --------------------- split-K combine + layer epilogue --------------------
// Sums nslab fp32 partial slabs, then:
// MODE 1: bias,relu,dropout -> half | MODE 2: bias, /64 -> half | MODE 3: *64, bias -> fp32
template <int MODE>
__global__ void combine_k(const float* __restrict__ P, const float* __restrict__ bias,
                          void* __restrict__ out, int Mn, int N, int nslab) {
    int i = blockIdx.x * blockDim.x + threadIdx.x;
    if (i >= Mn) return;
    float v = P[i];
    for (int s = 1; s < nslab; s++) v += P[(size_t)s * Mn + i];
    if (MODE == 1) {
        v += bias[i % N];
        v = fmaxf(v, 0.0f);
        v = ((g_mask[i >> 5] >> (i & 31)) & 1u) ? v * 2.0f : 0.0f;
        ((__half*)out)[i] = __float2half_rn(v);
    } else if (MODE == 2) {
        v += bias[i % N];
        ((__half*)out)[i] = __float2half_rn(v * X2_INV_SCALE);
    } else {
        v = v * X2_SCALE + bias[i % N];
        ((float*)out)[i] = v;
    }
}

// ------------------------------ launch -------------------------------------
extern "C" void kernel_launch(void* const* d_in, const int* in_sizes, int n_in,
                              void* d_out, int out_size) {
    const float* x   = (const float*)d_in[0];
    const float* adj = (const float*)d_in[1];
    const float* W1  = (const float*)d_in[2];
    const float* b1  = (const float*)d_in[3];
    const float* W2  = (const float*)d_in[4];
    const float* b2  = (const float*)d_in[5];
    const float* W3  = (const float*)d_in[6];
    const float* b3  = (const float*)d_in[7];
    float* out = (float*)d_out;

    __half *adjH, *xH, *w1t, *w2t, *w3t, *Ht, *X;
    float* P;
    cudaGetSymbolAddress((void**)&adjH, g_adj_h);
    cudaGetSymbolAddress((void**)&xH, g_x_h);
    cudaGetSymbolAddress((void**)&w1t, g_w1t);
    cudaGetSymbolAddress((void**)&w2t, g_w2t);
    cudaGetSymbolAddress((void**)&w3t, g_w3t);
    cudaGetSymbolAddress((void**)&Ht, g_Ht);
    cudaGetSymbolAddress((void**)&X, g_X);
    cudaGetSymbolAddress((void**)&P, g_P);

    const int M = MM, MT = (M + BM - 1) / BM;  // 79
    cudaFuncSetAttribute(gemm_h<true>,  cudaFuncAttributeMaxDynamicSharedMemorySize, SMEM_BYTES);
    cudaFuncSetAttribute(gemm_h<false>, cudaFuncAttributeMaxDynamicSharedMemorySize, SMEM_BYTES);

    dim3 blk(128);
    // split-K factors tuned for occ=3 (444 slots/wave): 1264 CTAs = 2.85 waves.
    // kLen values are multiples of 8 halves => z*kLen is 16B-aligned for cp.async.
    // launch order: ncu (-s 5 -c 1) profiles index 5 = L1 adj GEMM
    tohalf_k<<<4096, 256>>>(adj, (__half2*)adjH, M * (M / 4));                 // 0
    mask_k<<<(M * 512) / 256, 256>>>(M * 512);                                // 1
    tohalf_k<<<2048, 256>>>(x, (__half2*)xH, M * 256);                        // 2
    transpose_k<<<dim3(16, 32), dim3(32, 8)>>>(W1, w1t, 1024, 512);           // 3
    // L1: H1t = (x@W1)^T ; P = adj@H1 (split-K=2, kLen=5000) ; X1 = drop(relu(P+b1))
    gemm_h<true><<<dim3(8, MT, 1), blk, SMEM_BYTES>>>(xH, w1t, Ht, M, 512, 1024, 1024);   // 4
    gemm_h<false><<<dim3(8, MT, 2), blk, SMEM_BYTES>>>(adjH, Ht, P, M, 512, M, 5000);     // 5 <- ncu
    combine_k<1><<<(M * 512 + 255) / 256, 256>>>(P, b1, X, M * 512, 512, 2);  // 6
    // L2: H2t = (X1@W2)^T ; X2 = (adj@H2 + b2)/64, split-K=4 (kLen=2504)
    transpose_k<<<dim3(8, 16), dim3(32, 8)>>>(W2, w2t, 512, 256);             // 7
    gemm_h<true><<<dim3(4, MT, 1), blk, SMEM_BYTES>>>(X, w2t, Ht, M, 256, 512, 512);      // 8
    gemm_h<false><<<dim3(4, MT, 4), blk, SMEM_BYTES>>>(adjH, Ht, P, M, 256, M, 2504);     // 9
    combine_k<2><<<(M * 256 + 255) / 256, 256>>>(P, b2, X, M * 256, 256, 4);  // 10
    // L3: H3t = ((X2/64)@W3)^T ; out = 64*(adj@H3) + b3, split-K=8 (kLen=1256)
    transpose_k<<<dim3(4, 8), dim3(32, 8)>>>(W3, w3t, 256, 128);              // 11
    gemm_h<true><<<dim3(2, MT, 1), blk, SMEM_BYTES>>>(X, w3t, Ht, M, 128, 256, 256);      // 12
    gemm_h<false><<<dim3(2, MT, 8), blk, SMEM_BYTES>>>(adjH, Ht, P, M, 128, M, 1256);     // 13
    combine_k<3><<<(M * 128 + 255) / 256, 256>>>(P, b3, out, M * 128, 128, 8); // 14
}